// round 4
// baseline (speedup 1.0000x reference)
#include <cuda_runtime.h>
#include <cstdint>

#define C_INN 128
#define C_OUTT 64
#define BB 8
#define NN 2048
#define LOG2E 1.4426950408889634f

// ---------------------------------------------------------------------------
// Scratch (__device__ globals: allocation-free per harness rules)
// ---------------------------------------------------------------------------
__device__ float  g_Wh[BB * NN * C_OUTT];       // tf32-rounded Wh, 4 MB
__device__ float2 g_E1i[BB * NN];               // {exp(f1), exp(0.2 f1)}
__device__ float2 g_E2i[BB * NN];               // {exp(f2), exp(0.2 f2)}
__device__ unsigned g_Mt[(NN / 32) * NN];       // transposed bitmask [word][i]

__device__ __forceinline__ float fast_exp(float x) {
    float r;
    asm("ex2.approx.f32 %0, %1;" : "=f"(r) : "f"(x * LOG2E));
    return r;
}

__device__ __forceinline__ uint32_t cvt_tf32(float f) {
    uint32_t u;
    asm("cvt.rna.tf32.f32 %0, %1;" : "=r"(u) : "f"(f));
    return u;
}

// ---------------------------------------------------------------------------
// Kernel 1: Wh = x @ W, fully SMEM-staged. 256 thr = 8 warps x 8 rows = 64
// rows/CTA, grid 256. W interleaved float2{W[c][n], W[c][n+32]} -> LDS.64.
// Fused epilogue: f1/f2 reduction + exp tables; Wh stored tf32-rounded.
// ---------------------------------------------------------------------------
__global__ void __launch_bounds__(256) k_wh(const float* __restrict__ x,
                                            const float* __restrict__ W,
                                            const float* __restrict__ attn)
{
    extern __shared__ float sm[];
    float* Wsh = sm;          // 8192 floats: [c][lane] float2-interleaved
    float* xsh = sm + 8192;   // 8192 floats: [64][128]

    int t = threadIdx.x, warp = t >> 5, lane = t & 31;
    int base = blockIdx.x * 64;

    // stage W interleaved: Wsh[(c*32 + (n&31))*2 + (n>>5)] = W[c*64+n]
    #pragma unroll
    for (int k = 0; k < 32; k++) {
        int idx = t + k * 256;
        int c = idx >> 6, n = idx & 63;
        Wsh[(c * 32 + (n & 31)) * 2 + (n >> 5)] = W[idx];
    }
    // stage x: coalesced float4, MLP 8
    {
        const float4* xr = (const float4*)(x + (size_t)base * C_INN);
        float4* xd = (float4*)xsh;
        #pragma unroll
        for (int k = 0; k < 8; k++) xd[t + k * 256] = xr[t + k * 256];
    }
    __syncthreads();

    int r = warp * 8;
    float a0[8], a1[8];
    #pragma unroll
    for (int q = 0; q < 8; q++) { a0[q] = 0.f; a1[q] = 0.f; }

    #pragma unroll 4
    for (int c4 = 0; c4 < C_INN; c4 += 4) {
        float2 w0 = *(float2*)&Wsh[((c4 + 0) * 32 + lane) * 2];
        float2 w1 = *(float2*)&Wsh[((c4 + 1) * 32 + lane) * 2];
        float2 w2 = *(float2*)&Wsh[((c4 + 2) * 32 + lane) * 2];
        float2 w3 = *(float2*)&Wsh[((c4 + 3) * 32 + lane) * 2];
        #pragma unroll
        for (int q = 0; q < 8; q++) {
            float4 xv = *(const float4*)&xsh[(r + q) * C_INN + c4];
            a0[q] = fmaf(xv.x, w0.x, a0[q]); a1[q] = fmaf(xv.x, w0.y, a1[q]);
            a0[q] = fmaf(xv.y, w1.x, a0[q]); a1[q] = fmaf(xv.y, w1.y, a1[q]);
            a0[q] = fmaf(xv.z, w2.x, a0[q]); a1[q] = fmaf(xv.z, w2.y, a1[q]);
            a0[q] = fmaf(xv.w, w3.x, a0[q]); a1[q] = fmaf(xv.w, w3.y, a1[q]);
        }
    }

    float at1a = attn[lane], at1b = attn[32 + lane];
    float at2a = attn[64 + lane], at2b = attn[96 + lane];

    #pragma unroll
    for (int q = 0; q < 8; q++) {
        int row = base + r + q;
        float p1 = a0[q] * at1a + a1[q] * at1b;
        float p2 = a0[q] * at2a + a1[q] * at2b;
        #pragma unroll
        for (int s = 16; s; s >>= 1) {
            p1 += __shfl_xor_sync(0xffffffffu, p1, s);
            p2 += __shfl_xor_sync(0xffffffffu, p2, s);
        }
        if (lane == 0) {
            g_E1i[row] = make_float2(fast_exp(p1), fast_exp(0.2f * p1));
            g_E2i[row] = make_float2(fast_exp(p2), fast_exp(0.2f * p2));
        }
        g_Wh[(size_t)row * C_OUTT + lane]      = __uint_as_float(cvt_tf32(a0[q]));
        g_Wh[(size_t)row * C_OUTT + 32 + lane] = __uint_as_float(cvt_tf32(a1[q]));
    }
}

// ---------------------------------------------------------------------------
// Kernel 2: bit-pack mask, stored TRANSPOSED: g_Mt[word][i].
// ---------------------------------------------------------------------------
__global__ void __launch_bounds__(256) k_mask(const int* __restrict__ A)
{
    __shared__ unsigned char nib[256];
    int t = threadIdx.x;
    int i = blockIdx.x >> 1;
    int wb = (blockIdx.x & 1) * 32;
    int4 v = ((const int4*)A)[(size_t)blockIdx.x * 256 + t];
    unsigned n = (v.x > 0 ? 1u : 0u) | (v.y > 0 ? 2u : 0u) |
                 (v.z > 0 ? 4u : 0u) | (v.w > 0 ? 8u : 0u);
    nib[t] = (unsigned char)n;
    __syncthreads();
    if (t < 32) {
        const unsigned char* p = nib + t * 8;
        unsigned w = 0;
        #pragma unroll
        for (int s = 0; s < 8; s++) w |= ((unsigned)(p[s] & 0xFu)) << (4 * s);
        g_Mt[(size_t)(wb + t) * NN + i] = w;
    }
}

// ---------------------------------------------------------------------------
// Kernel 3: fused P-build + mma.sync tf32 aggregation.
// 512 thr = 16 warps (8 M x 2 N), warp tile M=16 N=32, 128 i-rows/CTA.
// Paired-j Wh tile: float2{Wh[j][n], Wh[j+4][n]}, row stride 68 float2
// (136 words == 8 mod 32 -> conflict-free 2-wavefront LDS.64 B loads).
// Paired E2 float4{E2[j],E2p[j],E2[j+4],E2p[j+4]} -> one LDS.128 per ks.
// ---------------------------------------------------------------------------
__global__ void __launch_bounds__(512, 1) k_gat(float* __restrict__ out)
{
    __shared__ float2   Whs2[64 * 68];    // 34816 B
    __shared__ float4   E2q[64];          // {E2[j],E2p[j],E2[j+4],E2p[j+4]}
    __shared__ unsigned Msh[4][128];
    __shared__ float    zsh[128];

    int t = threadIdx.x;
    int lane = t & 31, w = t >> 5;
    int warpM = w >> 1, nwarp = w & 1;
    int g = lane >> 2, tk = lane & 3;
    int b = blockIdx.x >> 4, i0 = (blockIdx.x & 15) << 7;
    int b2048 = b * NN;

    int r0 = warpM * 16 + g, r1 = r0 + 8;
    float2 e1a = g_E1i[b2048 + i0 + r0];
    float2 e1b = g_E1i[b2048 + i0 + r1];

    float c[4][4];
    #pragma unroll
    for (int nt = 0; nt < 4; nt++)
        #pragma unroll
        for (int k = 0; k < 4; k++) c[nt][k] = 0.f;
    float z0 = 0.f, z1 = 0.f;

    unsigned mt0 = 1u << tk;
    unsigned mt1 = 16u << tk;

    const float4* wh4 = (const float4*)(g_Wh + (size_t)b2048 * C_OUTT);

    // register prefetch buffers
    float4 pw[4]; unsigned pm; float2 pe;
    {
        #pragma unroll
        for (int k = 0; k < 4; k++) pw[k] = wh4[t + k * 512];
        pm = g_Mt[(size_t)(t >> 7) * NN + i0 + (t & 127)];
        if (t < 128) pe = g_E2i[b2048 + t];
    }

    for (int jt = 0; jt < 16; jt++) {
        __syncthreads();                       // previous compute done
        // stage prefetched tile into paired-j layout
        #pragma unroll
        for (int k = 0; k < 4; k++) {
            int idx = t + k * 512;
            int jl = idx >> 4, c4i = idx & 15;
            int p = (jl >> 3) * 4 + (jl & 3);
            int h = (jl >> 2) & 1;
            float* f = (float*)Whs2 + (p * 68 + c4i * 4) * 2 + h;
            f[0] = pw[k].x; f[2] = pw[k].y; f[4] = pw[k].z; f[6] = pw[k].w;
        }
        Msh[t >> 7][t & 127] = pm;
        if (t < 128) {
            int p = (t >> 3) * 4 + (t & 3);
            int h = (t >> 2) & 1;
            ((float2*)E2q)[p * 2 + h] = pe;
        }
        __syncthreads();

        // prefetch next tile (wrap at 15 -> harmless re-read of tile 0)
        {
            int jn = (jt + 1) & 15;
            #pragma unroll
            for (int k = 0; k < 4; k++) pw[k] = wh4[jn * 2048 + t + k * 512];
            pm = g_Mt[(size_t)(jn * 4 + (t >> 7)) * NN + i0 + (t & 127)];
            if (t < 128) pe = g_E2i[b2048 + jn * 128 + t];
        }

        // compute this j-tile: 16 k-steps of 8 j's
        unsigned mw0 = 0, mw1 = 0;
        #pragma unroll
        for (int ks = 0; ks < 16; ks++) {
            if ((ks & 3) == 0) {
                mw0 = Msh[ks >> 2][r0];
                mw1 = Msh[ks >> 2][r1];
            }
            float4 e = E2q[ks * 4 + tk];
            unsigned s0 = mt0 << ((ks & 3) * 8);
            unsigned s1 = mt1 << ((ks & 3) * 8);

            float m;
            m = fmaxf(e1a.x * e.x, e1a.y * e.y);
            float a0 = (mw0 & s0) ? m : 0.f;
            m = fmaxf(e1b.x * e.x, e1b.y * e.y);
            float a1 = (mw1 & s0) ? m : 0.f;
            m = fmaxf(e1a.x * e.z, e1a.y * e.w);
            float a2 = (mw0 & s1) ? m : 0.f;
            m = fmaxf(e1b.x * e.z, e1b.y * e.w);
            float a3 = (mw1 & s1) ? m : 0.f;

            z0 += a0 + a2;
            z1 += a1 + a3;

            uint32_t ua0 = __float_as_uint(a0), ua1 = __float_as_uint(a1);
            uint32_t ua2 = __float_as_uint(a2), ua3 = __float_as_uint(a3);

            const float2* brow = Whs2 + (ks * 4 + tk) * 68 + nwarp * 32 + g;
            #pragma unroll
            for (int nt = 0; nt < 4; nt++) {
                float2 bv = brow[nt * 8];
                uint32_t ub0 = __float_as_uint(bv.x);
                uint32_t ub1 = __float_as_uint(bv.y);
                asm volatile(
                    "mma.sync.aligned.m16n8k8.row.col.f32.tf32.tf32.f32 "
                    "{%0,%1,%2,%3}, {%4,%5,%6,%7}, {%8,%9}, {%0,%1,%2,%3};"
                    : "+f"(c[nt][0]), "+f"(c[nt][1]), "+f"(c[nt][2]), "+f"(c[nt][3])
                    : "r"(ua0), "r"(ua1), "r"(ua2), "r"(ua3), "r"(ub0), "r"(ub1));
            }
        }
    }

    // per-row Z: reduce over the 4 tk lanes
    z0 += __shfl_xor_sync(0xffffffffu, z0, 1);
    z0 += __shfl_xor_sync(0xffffffffu, z0, 2);
    z1 += __shfl_xor_sync(0xffffffffu, z1, 1);
    z1 += __shfl_xor_sync(0xffffffffu, z1, 2);
    if (nwarp == 0 && tk == 0) { zsh[r0] = z0; zsh[r1] = z1; }
    __syncthreads();

    float inv0 = 1.f / zsh[r0];
    float inv1 = 1.f / zsh[r1];

    float* o0 = out + (size_t)(b2048 + i0 + r0) * C_OUTT + nwarp * 32 + tk * 2;
    float* o1 = out + (size_t)(b2048 + i0 + r1) * C_OUTT + nwarp * 32 + tk * 2;
    #pragma unroll
    for (int nt = 0; nt < 4; nt++) {
        *(float2*)(o0 + nt * 8) = make_float2(c[nt][0] * inv0, c[nt][1] * inv0);
        *(float2*)(o1 + nt * 8) = make_float2(c[nt][2] * inv1, c[nt][3] * inv1);
    }
}

// ---------------------------------------------------------------------------
extern "C" void kernel_launch(void* const* d_in, const int* in_sizes, int n_in,
                              void* d_out, int out_size)
{
    const float* x    = (const float*)d_in[0];   // (8,2048,128) f32
    const int*   A    = (const int*)d_in[1];     // (2048,2048) i32
    const float* W    = (const float*)d_in[2];   // (128,64) f32
    const float* attn = (const float*)d_in[3];   // (128,1) f32
    float* out = (float*)d_out;                  // (8,2048,64) f32

    cudaFuncSetAttribute(k_wh, cudaFuncAttributeMaxDynamicSharedMemorySize, 65536);

    k_wh  <<<BB * NN / 64, 256, 65536>>>(x, W, attn);
    k_mask<<<NN * NN / 1024, 256>>>(A);
    k_gat <<<BB * (NN / 128), 512>>>(out);
}

// round 5
// speedup vs baseline: 1.4230x; 1.4230x over previous
#include <cuda_runtime.h>
#include <cstdint>

#define C_INN 128
#define C_OUTT 64
#define BB 8
#define NN 2048
#define LOG2E 1.4426950408889634f

// ---------------------------------------------------------------------------
// Scratch (__device__ globals: allocation-free per harness rules)
// ---------------------------------------------------------------------------
__device__ float  g_Wh[BB * NN * C_OUTT];       // tf32-rounded Wh, 4 MB
__device__ float2 g_E1i[BB * NN];               // {exp(f1), exp(0.2 f1)}
__device__ float2 g_E2i[BB * NN];               // {exp(f2), exp(0.2 f2)}
__device__ unsigned g_Mt[(NN / 32) * NN];       // transposed bitmask [word][i]

__device__ __forceinline__ float fast_exp(float x) {
    float r;
    asm("ex2.approx.f32 %0, %1;" : "=f"(r) : "f"(x * LOG2E));
    return r;
}

__device__ __forceinline__ uint32_t cvt_tf32(float f) {
    uint32_t u;
    asm("cvt.rna.tf32.f32 %0, %1;" : "=r"(u) : "f"(f));
    return u;
}

// ---------------------------------------------------------------------------
// Kernel 1: Wh = x @ W, fully SMEM-staged (R4 version, 15.7us measured).
// ---------------------------------------------------------------------------
__global__ void __launch_bounds__(256) k_wh(const float* __restrict__ x,
                                            const float* __restrict__ W,
                                            const float* __restrict__ attn)
{
    extern __shared__ float sm[];
    float* Wsh = sm;          // 8192 floats: [c][lane] float2-interleaved
    float* xsh = sm + 8192;   // 8192 floats: [64][128]

    int t = threadIdx.x, warp = t >> 5, lane = t & 31;
    int base = blockIdx.x * 64;

    #pragma unroll
    for (int k = 0; k < 32; k++) {
        int idx = t + k * 256;
        int c = idx >> 6, n = idx & 63;
        Wsh[(c * 32 + (n & 31)) * 2 + (n >> 5)] = W[idx];
    }
    {
        const float4* xr = (const float4*)(x + (size_t)base * C_INN);
        float4* xd = (float4*)xsh;
        #pragma unroll
        for (int k = 0; k < 8; k++) xd[t + k * 256] = xr[t + k * 256];
    }
    __syncthreads();

    int r = warp * 8;
    float a0[8], a1[8];
    #pragma unroll
    for (int q = 0; q < 8; q++) { a0[q] = 0.f; a1[q] = 0.f; }

    #pragma unroll 4
    for (int c4 = 0; c4 < C_INN; c4 += 4) {
        float2 w0 = *(float2*)&Wsh[((c4 + 0) * 32 + lane) * 2];
        float2 w1 = *(float2*)&Wsh[((c4 + 1) * 32 + lane) * 2];
        float2 w2 = *(float2*)&Wsh[((c4 + 2) * 32 + lane) * 2];
        float2 w3 = *(float2*)&Wsh[((c4 + 3) * 32 + lane) * 2];
        #pragma unroll
        for (int q = 0; q < 8; q++) {
            float4 xv = *(const float4*)&xsh[(r + q) * C_INN + c4];
            a0[q] = fmaf(xv.x, w0.x, a0[q]); a1[q] = fmaf(xv.x, w0.y, a1[q]);
            a0[q] = fmaf(xv.y, w1.x, a0[q]); a1[q] = fmaf(xv.y, w1.y, a1[q]);
            a0[q] = fmaf(xv.z, w2.x, a0[q]); a1[q] = fmaf(xv.z, w2.y, a1[q]);
            a0[q] = fmaf(xv.w, w3.x, a0[q]); a1[q] = fmaf(xv.w, w3.y, a1[q]);
        }
    }

    float at1a = attn[lane], at1b = attn[32 + lane];
    float at2a = attn[64 + lane], at2b = attn[96 + lane];

    #pragma unroll
    for (int q = 0; q < 8; q++) {
        int row = base + r + q;
        float p1 = a0[q] * at1a + a1[q] * at1b;
        float p2 = a0[q] * at2a + a1[q] * at2b;
        #pragma unroll
        for (int s = 16; s; s >>= 1) {
            p1 += __shfl_xor_sync(0xffffffffu, p1, s);
            p2 += __shfl_xor_sync(0xffffffffu, p2, s);
        }
        if (lane == 0) {
            g_E1i[row] = make_float2(fast_exp(p1), fast_exp(0.2f * p1));
            g_E2i[row] = make_float2(fast_exp(p2), fast_exp(0.2f * p2));
        }
        g_Wh[(size_t)row * C_OUTT + lane]      = __uint_as_float(cvt_tf32(a0[q]));
        g_Wh[(size_t)row * C_OUTT + 32 + lane] = __uint_as_float(cvt_tf32(a1[q]));
    }
}

// ---------------------------------------------------------------------------
// Kernel 2: bit-pack mask, stored TRANSPOSED: g_Mt[word][i].
// ---------------------------------------------------------------------------
__global__ void __launch_bounds__(256) k_mask(const int* __restrict__ A)
{
    __shared__ unsigned char nib[256];
    int t = threadIdx.x;
    int i = blockIdx.x >> 1;
    int wb = (blockIdx.x & 1) * 32;
    int4 v = ((const int4*)A)[(size_t)blockIdx.x * 256 + t];
    unsigned n = (v.x > 0 ? 1u : 0u) | (v.y > 0 ? 2u : 0u) |
                 (v.z > 0 ? 4u : 0u) | (v.w > 0 ? 8u : 0u);
    nib[t] = (unsigned char)n;
    __syncthreads();
    if (t < 32) {
        const unsigned char* p = nib + t * 8;
        unsigned w = 0;
        #pragma unroll
        for (int s = 0; s < 8; s++) w |= ((unsigned)(p[s] & 0xFu)) << (4 * s);
        g_Mt[(size_t)(wb + t) * NN + i] = w;
    }
}

// ---------------------------------------------------------------------------
// Kernel 3: fused P-build + mma.sync tf32 aggregation, K-split warp pairs.
// 512 thr = 16 warps = 8 warpM x 2 kwarp. Warp tile: M=16, N=64, half the
// k-steps (kwarp 0: ks 0-7, kwarp 1: ks 8-15 per j-tile). P fragments are
// computed exactly once per (i,j) CTA-wide. Wh tile in R3's proven [j][n]
// stride-72 SMEM layout (STS.128 staging, conflict-free LDS.32 B loads).
// Epilogue: kwarp-1 dumps partial accumulators (float4, conflict-free) into
// reused Whs; kwarp-0 adds, normalizes by Z, writes out.
// ---------------------------------------------------------------------------
__global__ void __launch_bounds__(512, 1) k_gat(float* __restrict__ out)
{
    __shared__ float    Whs[128 * 72];   // 36864 B; reused as reduction buffer
    __shared__ float2   E2s[128];
    __shared__ unsigned Msh[4][128];

    int t = threadIdx.x;
    int lane = t & 31, w = t >> 5;
    int warpM = w >> 1, kwarp = w & 1;
    int g = lane >> 2, tk = lane & 3;
    int b = blockIdx.x >> 4, i0 = (blockIdx.x & 15) << 7;
    int b2048 = b * NN;

    int r0 = warpM * 16 + g, r1 = r0 + 8;
    float2 e1a = g_E1i[b2048 + i0 + r0];
    float2 e1b = g_E1i[b2048 + i0 + r1];

    float c[8][4];
    #pragma unroll
    for (int nt = 0; nt < 8; nt++)
        #pragma unroll
        for (int k = 0; k < 4; k++) c[nt][k] = 0.f;
    float z0 = 0.f, z1 = 0.f;

    unsigned mt0 = 1u << tk;
    unsigned mt1 = 16u << tk;

    const float4* wh4 = (const float4*)(g_Wh + (size_t)b2048 * C_OUTT);

    // register prefetch buffers
    float4 pw[4]; unsigned pm; float2 pe;
    {
        #pragma unroll
        for (int k = 0; k < 4; k++) pw[k] = wh4[t + k * 512];
        pm = g_Mt[(size_t)(t >> 7) * NN + i0 + (t & 127)];
        if (t < 128) pe = g_E2i[b2048 + t];
    }

    for (int jt = 0; jt < 16; jt++) {
        __syncthreads();                       // previous compute done
        #pragma unroll
        for (int k = 0; k < 4; k++) {
            int idx = t + k * 512;
            *(float4*)&Whs[(idx >> 4) * 72 + ((idx & 15) << 2)] = pw[k];
        }
        Msh[t >> 7][t & 127] = pm;
        if (t < 128) E2s[t] = pe;
        __syncthreads();

        // prefetch next tile (wrap at 15 -> harmless re-read of tile 0)
        {
            int jn = (jt + 1) & 15;
            #pragma unroll
            for (int k = 0; k < 4; k++) pw[k] = wh4[jn * 2048 + t + k * 512];
            pm = g_Mt[(size_t)(jn * 4 + (t >> 7)) * NN + i0 + (t & 127)];
            if (t < 128) pe = g_E2i[b2048 + jn * 128 + t];
        }

        // this warp's 8 k-steps (kwarp selects which half of the j-tile)
        unsigned mw0 = 0, mw1 = 0;
        #pragma unroll
        for (int ks = 0; ks < 8; ks++) {
            int ksg = kwarp * 8 + ks;
            if ((ks & 3) == 0) {
                mw0 = Msh[kwarp * 2 + (ks >> 2)][r0];
                mw1 = Msh[kwarp * 2 + (ks >> 2)][r1];
            }
            int j0 = ksg * 8;
            float2 ea = E2s[j0 + tk];
            float2 eb = E2s[j0 + tk + 4];
            unsigned s0 = mt0 << ((ks & 3) * 8);
            unsigned s1 = mt1 << ((ks & 3) * 8);

            float m;
            m = fmaxf(e1a.x * ea.x, e1a.y * ea.y);
            float a0 = (mw0 & s0) ? m : 0.f;
            m = fmaxf(e1b.x * ea.x, e1b.y * ea.y);
            float a1 = (mw1 & s0) ? m : 0.f;
            m = fmaxf(e1a.x * eb.x, e1a.y * eb.y);
            float a2 = (mw0 & s1) ? m : 0.f;
            m = fmaxf(e1b.x * eb.x, e1b.y * eb.y);
            float a3 = (mw1 & s1) ? m : 0.f;

            z0 += a0 + a2;
            z1 += a1 + a3;

            uint32_t ua0 = __float_as_uint(a0), ua1 = __float_as_uint(a1);
            uint32_t ua2 = __float_as_uint(a2), ua3 = __float_as_uint(a3);

            const float* brow = Whs + (j0 + tk) * 72 + g;
            #pragma unroll
            for (int nt = 0; nt < 8; nt++) {
                uint32_t ub0 = __float_as_uint(brow[nt * 8]);
                uint32_t ub1 = __float_as_uint(brow[288 + nt * 8]);
                asm volatile(
                    "mma.sync.aligned.m16n8k8.row.col.f32.tf32.tf32.f32 "
                    "{%0,%1,%2,%3}, {%4,%5,%6,%7}, {%8,%9}, {%0,%1,%2,%3};"
                    : "+f"(c[nt][0]), "+f"(c[nt][1]), "+f"(c[nt][2]), "+f"(c[nt][3])
                    : "r"(ua0), "r"(ua1), "r"(ua2), "r"(ua3), "r"(ub0), "r"(ub1));
            }
        }
    }

    // intra-warp Z reduce over the 4 tk lanes (all lanes end with row sums)
    z0 += __shfl_xor_sync(0xffffffffu, z0, 1);
    z0 += __shfl_xor_sync(0xffffffffu, z0, 2);
    z1 += __shfl_xor_sync(0xffffffffu, z1, 1);
    z1 += __shfl_xor_sync(0xffffffffu, z1, 2);

    // cross-kwarp reduction through reused Whs (safe after sync)
    __syncthreads();
    float4* red4 = (float4*)Whs;                       // [warpM][nt][lane]
    float2* zred = (float2*)(Whs + 32768 / 4 * 4);     // after 32KB
    // (32768 bytes = 8*8*32*16); zred occupies next 2KB of Whs region
    zred = (float2*)((char*)Whs + 32768);

    if (kwarp == 1) {
        #pragma unroll
        for (int nt = 0; nt < 8; nt++)
            red4[(warpM * 8 + nt) * 32 + lane] =
                make_float4(c[nt][0], c[nt][1], c[nt][2], c[nt][3]);
        zred[warpM * 32 + lane] = make_float2(z0, z1);
    }
    __syncthreads();

    if (kwarp == 0) {
        float2 zz = zred[warpM * 32 + lane];
        float inv0 = 1.f / (z0 + zz.x);
        float inv1 = 1.f / (z1 + zz.y);

        float* o0 = out + (size_t)(b2048 + i0 + r0) * C_OUTT + tk * 2;
        float* o1 = out + (size_t)(b2048 + i0 + r1) * C_OUTT + tk * 2;
        #pragma unroll
        for (int nt = 0; nt < 8; nt++) {
            float4 v = red4[(warpM * 8 + nt) * 32 + lane];
            *(float2*)(o0 + nt * 8) =
                make_float2((c[nt][0] + v.x) * inv0, (c[nt][1] + v.y) * inv0);
            *(float2*)(o1 + nt * 8) =
                make_float2((c[nt][2] + v.z) * inv1, (c[nt][3] + v.w) * inv1);
        }
    }
}

// ---------------------------------------------------------------------------
extern "C" void kernel_launch(void* const* d_in, const int* in_sizes, int n_in,
                              void* d_out, int out_size)
{
    const float* x    = (const float*)d_in[0];   // (8,2048,128) f32
    const int*   A    = (const int*)d_in[1];     // (2048,2048) i32
    const float* W    = (const float*)d_in[2];   // (128,64) f32
    const float* attn = (const float*)d_in[3];   // (128,1) f32
    float* out = (float*)d_out;                  // (8,2048,64) f32

    cudaFuncSetAttribute(k_wh, cudaFuncAttributeMaxDynamicSharedMemorySize, 65536);

    k_wh  <<<BB * NN / 64, 256, 65536>>>(x, W, attn);
    k_mask<<<NN * NN / 1024, 256>>>(A);
    k_gat <<<BB * (NN / 128), 512>>>(out);
}